// round 12
// baseline (speedup 1.0000x reference)
#include <cuda_runtime.h>
#include <cuda_bf16.h>
#include <cstdint>

// ---------------- problem constants ----------------
#define SEQ   2048
#define EDIM  512
#define HDIM  256
#define TTAGS 32
#define TSTART 30
#define TSTOP  31
#define NEGV  (-10000.0f)

// ---------------- device scratch (no allocs allowed) ----------------
__device__ float g_px[2][SEQ][1024];     // input projections (bias fused), per dir
__device__ float g_h[2][SEQ][HDIM];      // lstm hidden outputs, per dir
__device__ float g_feats[SEQ][TTAGS];    // tag scores
__device__ float g_wtagT[EDIM][TTAGS];   // transposed tag weights
__device__ int   g_bptr[SEQ][TTAGS];     // viterbi backpointers

// ---------------- small helpers ----------------
__device__ __forceinline__ unsigned long long pack2f(float x, float y) {
    unsigned long long r;
    asm("mov.b64 %0, {%1, %2};" : "=l"(r) : "f"(x), "f"(y));
    return r;
}
__device__ __forceinline__ float2 unpack2f(unsigned long long v) {
    float2 r;
    asm("mov.b64 {%0, %1}, %2;" : "=f"(r.x), "=f"(r.y) : "l"(v));
    return r;
}
__device__ __forceinline__ void fma2(unsigned long long& d, unsigned long long a,
                                     unsigned long long b) {
    asm("fma.rn.f32x2 %0, %1, %2, %0;" : "+l"(d) : "l"(a), "l"(b));
}
__device__ __forceinline__ unsigned smem_u32(const void* p) {
    unsigned a;
    asm("{ .reg .u64 t; cvta.to.shared.u64 t, %1; cvt.u32.u64 %0, t; }"
        : "=r"(a) : "l"(p));
    return a;
}
__device__ __forceinline__ unsigned mapa_u32(unsigned addr, int rank) {
    unsigned ra;
    asm("mapa.shared::cluster.u32 %0, %1, %2;" : "=r"(ra) : "r"(addr), "r"(rank));
    return ra;
}
// weak data store into a peer CTA's smem
__device__ __forceinline__ void st_weak_cluster_f32(unsigned raddr, float v) {
    asm volatile("st.shared::cluster.f32 [%0], %1;" :: "r"(raddr), "f"(v)
                 : "memory");
}
// release token store: orders THIS thread's prior stores for any acquirer
__device__ __forceinline__ void st_rel_cluster_u32(unsigned raddr, unsigned v) {
    asm volatile("st.release.cluster.shared::cluster.u32 [%0], %1;"
                 :: "r"(raddr), "r"(v) : "memory");
}
__device__ __forceinline__ unsigned ld_acq_u32(unsigned addr) {
    unsigned v;
    asm volatile("ld.acquire.cluster.shared::cta.u32 %0, [%1];"
                 : "=r"(v) : "r"(addr) : "memory");
    return v;
}
__device__ __forceinline__ void cluster_sync_() {
    asm volatile("barrier.cluster.arrive.aligned;" ::: "memory");
    asm volatile("barrier.cluster.wait.aligned;" ::: "memory");
}
__device__ __forceinline__ float sigmoidf_(float x) {
    return 1.0f / (1.0f + __expf(-x));
}

// ============================================================================
// Kernel 1: px[dir][t][row] = sum_e emb[sent[t]][e] * w_ih[dir][row][e] + b[row]
// 64x64 output tile, K-tile 16, 256 threads, 4x4 microtile.
// ============================================================================
__global__ __launch_bounds__(256)
void px_gemm(const int* __restrict__ sent, const float* __restrict__ embed,
             const float* __restrict__ w_ih_f, const float* __restrict__ b_f,
             const float* __restrict__ w_ih_b, const float* __restrict__ b_b)
{
    int dir = blockIdx.z;
    const float* W  = dir ? w_ih_b : w_ih_f;
    const float* Bv = dir ? b_b    : b_f;
    int t0 = blockIdx.x * 64;
    int r0 = blockIdx.y * 64;

    __shared__ float As[16][64];
    __shared__ float Bs[16][68];
    __shared__ int   ssent[64];

    int tid = threadIdx.x;
    if (tid < 64) ssent[tid] = sent[t0 + tid];
    __syncthreads();

    int tx = tid & 15, ty = tid >> 4;
    float acc[4][4] = {};

    for (int k0 = 0; k0 < EDIM; k0 += 16) {
#pragma unroll
        for (int l = 0; l < 4; l++) {
            int lin = tid + l * 256;
            int kk = lin & 15, ii = lin >> 4;
            As[kk][ii] = embed[(size_t)ssent[ii] * EDIM + k0 + kk];
            Bs[kk][ii] = W[(size_t)(r0 + ii) * EDIM + k0 + kk];
        }
        __syncthreads();
#pragma unroll
        for (int kk = 0; kk < 16; kk++) {
            float a[4], b[4];
#pragma unroll
            for (int i = 0; i < 4; i++) a[i] = As[kk][ty * 4 + i];
#pragma unroll
            for (int j = 0; j < 4; j++) b[j] = Bs[kk][tx * 4 + j];
#pragma unroll
            for (int i = 0; i < 4; i++)
#pragma unroll
                for (int j = 0; j < 4; j++) acc[i][j] += a[i] * b[j];
        }
        __syncthreads();
    }
#pragma unroll
    for (int i = 0; i < 4; i++)
#pragma unroll
        for (int j = 0; j < 4; j++) {
            int t = t0 + ty * 4 + i;
            int r = r0 + tx * 4 + j;
            g_px[dir][t][r] = acc[i][j] + Bv[r];
        }
}

// ============================================================================
// Kernel 2: transpose w_tag [32,512] -> g_wtagT [512,32]
// ============================================================================
__global__ void wtagT_kernel(const float* __restrict__ w_tag)
{
    int idx = blockIdx.x * blockDim.x + threadIdx.x;
    if (idx < TTAGS * EDIM) {
        int tag = idx >> 9;
        int e   = idx & 511;
        g_wtagT[e][tag] = w_tag[idx];
    }
}

// ============================================================================
// Kernel 3: BiLSTM recurrence. Base = the 2875us best (merged warp0 reduce).
// ONE change: in-loop cluster.sync replaced by per-unit release/acquire
// token handshake with NO shared sync object and NO fences:
//   warp0 lane u, per peer cc: weak h store, then st.release token (step+1)
//   to tok_sh[wb][unit] in peer cc. Same-thread program order means the
//   release orders that lane's own data store -- no cross-lane fence needed.
//   Threads 256..511 each acquire-poll ONE token word (>= step+1), then one
//   __syncthreads publishes everything CTA-wide.
// Why safe: release-store -> acquire-load -> __syncthreads is a full
// happens-before chain for the h data; WAR on h_sh/red_sh holds because a
// peer's step-(s+1) stores require its step-s poll, which requires OUR
// step-s tokens, which warp0 writes only after this CTA's post-matvec
// __syncthreads (i.e. after all our reads of the target buffer).
// 256 independent flag words => no serialization point (the failure mode of
// both mbarrier variants). Pollers are warps 8-15 so warp0's tail contends
// only with parked warps (hi-wid-first arbiter).
// ============================================================================
__global__ void __cluster_dims__(8, 1, 1) __launch_bounds__(512, 1)
lstm_kernel(const float* __restrict__ w_hh_f, const float* __restrict__ w_hh_b,
            const float* __restrict__ h0, const float* __restrict__ c0)
{
    int dir  = blockIdx.x >> 3;
    int rank = blockIdx.x & 7;
    const float* W  = dir ? w_hh_b : w_hh_f;
    const float* px = &g_px[dir][0][0];
    float* hout     = &g_h[dir][0][0];

    int tid  = threadIdx.x;
    int ks   = tid >> 7;        // 0..3  (k slice of 64)
    int r    = tid & 127;       // 0..127 (gate row within CTA)
    int grow = (r >> 5) * 256 + rank * 32 + (r & 31);   // gate row in [0,1024)

    __shared__ __align__(16) float h_sh[2][HDIM];
    __shared__ float red_sh[4][128];
    __shared__ __align__(16) unsigned tok_sh[2][HDIM];

    // load weight slice into registers, packed as f32x2
    unsigned long long w2[32];
    {
        const float2* wp = (const float2*)(W + (size_t)grow * HDIM + ks * 64);
#pragma unroll
        for (int i = 0; i < 32; i++) {
            float2 v = wp[i];
            w2[i] = pack2f(v.x, v.y);
        }
    }

    // initial state + zero tokens
    if (tid < HDIM) {
        h_sh[0][tid] = h0[dir * HDIM + tid];
        tok_sh[0][tid] = 0u;
        tok_sh[1][tid] = 0u;
    }
    float c = 0.0f;
    if (tid < 32) c = c0[dir * HDIM + rank * 32 + tid];

    // hoisted remote base addresses (h and token arrays) for all 8 ranks
    unsigned hbase = smem_u32(&h_sh[0][0]);
    unsigned tbase = smem_u32(&tok_sh[0][0]);
    unsigned rbase_h[8], rbase_t[8];
#pragma unroll
    for (int cc = 0; cc < 8; cc++) {
        rbase_h[cc] = mapa_u32(hbase, cc);
        rbase_t[cc] = mapa_u32(tbase, cc);
    }

    // warp0: prefetch px for step 0 (the 4 gate rows of unit `tid`)
    float px4_0 = 0.f, px4_1 = 0.f, px4_2 = 0.f, px4_3 = 0.f;
    if (tid < 32) {
        int t0i = dir ? (SEQ - 1) : 0;
        const float* p0 = &px[(size_t)t0i * 1024 + rank * 32 + tid];
        px4_0 = __ldg(p0);
        px4_1 = __ldg(p0 + 256);
        px4_2 = __ldg(p0 + 512);
        px4_3 = __ldg(p0 + 768);
    }

    __syncthreads();
    cluster_sync_();   // h_sh[0] + zeroed tokens visible cluster-wide

    int p = 0;
    for (int step = 0; step < SEQ; ++step) {
        int t = dir ? (SEQ - 1 - step) : step;
        int q = p ^ 1;   // buffer written this step

        // matvec partial: 64 MACs via 32 packed FFMA2 (identical to 2875 base)
        unsigned long long a0 = 0ull, a1 = 0ull;
        const ulonglong2* hp = (const ulonglong2*)&h_sh[p][ks * 64];
#pragma unroll
        for (int i = 0; i < 16; i += 2) {
            ulonglong2 u = hp[i];
            ulonglong2 v = hp[i + 1];
            fma2(a0, w2[2 * i], u.x);
            fma2(a1, w2[2 * i + 1], u.y);
            fma2(a0, w2[2 * i + 2], v.x);
            fma2(a1, w2[2 * i + 3], v.y);
        }
        float2 f0 = unpack2f(a0), f1 = unpack2f(a1);
        red_sh[ks][r] = (f0.x + f0.y) + (f1.x + f1.y);
        __syncthreads();

        // warp0: reduce all 4 gates + activations + cell/hidden + broadcast
        if (tid < 32) {
            float v0 = red_sh[0][tid]      + red_sh[1][tid]      +
                       red_sh[2][tid]      + red_sh[3][tid]      + px4_0;
            float v1 = red_sh[0][32 + tid] + red_sh[1][32 + tid] +
                       red_sh[2][32 + tid] + red_sh[3][32 + tid] + px4_1;
            float v2 = red_sh[0][64 + tid] + red_sh[1][64 + tid] +
                       red_sh[2][64 + tid] + red_sh[3][64 + tid] + px4_2;
            float v3 = red_sh[0][96 + tid] + red_sh[1][96 + tid] +
                       red_sh[2][96 + tid] + red_sh[3][96 + tid] + px4_3;
            float ai = sigmoidf_(v0);
            float af = sigmoidf_(v1);
            float ag = tanhf(v2);
            float ao = sigmoidf_(v3);
            c = af * c + ai * ag;
            float hn = ao * tanhf(c);

            // per-peer: weak h store then release token store (same thread,
            // program order => data ordered before token for that peer)
            unsigned off_h = (unsigned)((q * HDIM + rank * 32 + tid) * 4);
            unsigned off_t = off_h;            // same layout for tok_sh
            unsigned tok   = (unsigned)(step + 1);
#pragma unroll
            for (int cc = 0; cc < 8; cc++) {
                st_weak_cluster_f32(rbase_h[cc] + off_h, hn);
                st_rel_cluster_u32(rbase_t[cc] + off_t, tok);
            }

            // off the critical path: global h store + next-step px prefetch
            hout[(size_t)t * HDIM + rank * 32 + tid] = hn;
            if (step + 1 < SEQ) {
                int tn = dir ? (SEQ - 2 - step) : (step + 1);
                const float* p0 = &px[(size_t)tn * 1024 + rank * 32 + tid];
                px4_0 = __ldg(p0);
                px4_1 = __ldg(p0 + 256);
                px4_2 = __ldg(p0 + 512);
                px4_3 = __ldg(p0 + 768);
            }
        }

        // threads 256..511 acquire-poll one token word each for buffer q
        if (tid >= 256) {
            unsigned a = tbase + (unsigned)((q * HDIM + (tid - 256)) * 4);
            unsigned want = (unsigned)(step + 1);
            while (ld_acq_u32(a) < want) {}
        }
        __syncthreads();   // publish h_sh[q] CTA-wide, protect red_sh WAR
        p = q;
    }
}

// ============================================================================
// Kernel 4: feats[t][tag] = [h_f(t) | h_b(t)] . w_tag[tag] + b_tag[tag]
// one block per timestep, 128 threads (32 tags x 4 partials)
// ============================================================================
__global__ __launch_bounds__(128)
void proj_kernel(const float* __restrict__ b_tag)
{
    int t = blockIdx.x;
    __shared__ float hs[2 * HDIM];
    __shared__ float red[4][TTAGS];
    int tid = threadIdx.x;
    for (int i = tid; i < HDIM; i += 128) {
        hs[i]        = g_h[0][t][i];
        hs[HDIM + i] = g_h[1][t][i];
    }
    __syncthreads();
    int tag = tid & 31, part = tid >> 5;
    float s = 0.0f;
    const float* hv = hs + part * 128;
    const float* wT = &g_wtagT[part * 128][tag];
#pragma unroll 8
    for (int j = 0; j < 128; j++) s += hv[j] * wT[j * TTAGS];
    red[part][tag] = s;
    __syncthreads();
    if (tid < TTAGS)
        g_feats[t][tid] = red[0][tid] + red[1][tid] + red[2][tid] + red[3][tid] +
                          b_tag[tid];
}

// ============================================================================
// Kernel 5: Viterbi forward + backtrack. Single warp (feat prefetch kept).
// ============================================================================
__global__ __launch_bounds__(32)
void viterbi_kernel(const float* __restrict__ trans, float* __restrict__ out,
                    int out_size)
{
    const unsigned FULL = 0xffffffffu;
    int lane = threadIdx.x;

    float tr[TTAGS];
#pragma unroll
    for (int j = 0; j < TTAGS; j++) tr[j] = trans[lane * TTAGS + j];

    float fv = (lane == TSTART) ? 0.0f : NEGV;
    float feat = g_feats[0][lane];

    for (int t = 0; t < SEQ; t++) {
        float feat_next = (t + 1 < SEQ) ? g_feats[t + 1][lane] : 0.0f;
        float b0 = -1e30f, b1 = -1e30f, b2 = -1e30f, b3 = -1e30f;
        int i0 = 0, i1 = 8, i2 = 16, i3 = 24;
#pragma unroll
        for (int j = 0; j < 8; j++) {
            float s0 = __shfl_sync(FULL, fv, j)      + tr[j];
            float s1 = __shfl_sync(FULL, fv, j + 8)  + tr[j + 8];
            float s2 = __shfl_sync(FULL, fv, j + 16) + tr[j + 16];
            float s3 = __shfl_sync(FULL, fv, j + 24) + tr[j + 24];
            if (s0 > b0) { b0 = s0; i0 = j; }
            if (s1 > b1) { b1 = s1; i1 = j + 8; }
            if (s2 > b2) { b2 = s2; i2 = j + 16; }
            if (s3 > b3) { b3 = s3; i3 = j + 24; }
        }
        float best = b0; int bj = i0;
        if (b1 > best) { best = b1; bj = i1; }
        if (b2 > best) { best = b2; bj = i2; }
        if (b3 > best) { best = b3; bj = i3; }
        g_bptr[t][lane] = bj;
        fv = best + feat;
        feat = feat_next;
    }

    // terminal: fv + transitions[STOP][prev]
    float term = fv + trans[TSTOP * TTAGS + lane];
    float bv = term; int bi = lane;
#pragma unroll
    for (int off = 16; off >= 1; off >>= 1) {
        float ov = __shfl_xor_sync(FULL, bv, off);
        int   oi = __shfl_xor_sync(FULL, bi, off);
        if (ov > bv || (ov == bv && oi < bi)) { bv = ov; bi = oi; }
    }
    if (lane == 0 && out_size > 0) out[0] = bv;

    // backtrack: tag_seq[S-1] = best_last; tag_seq[t-1] = bptr[t][tag_seq[t]]
    int tag = bi;
    for (int t0 = SEQ - 16; t0 >= 0; t0 -= 16) {
        int rows[16];
#pragma unroll
        for (int k = 0; k < 16; k++) rows[k] = g_bptr[t0 + k][lane];
#pragma unroll
        for (int k = 15; k >= 0; k--) {
            int t = t0 + k;
            if (lane == 0 && 1 + t < out_size) out[1 + t] = (float)tag;
            tag = __shfl_sync(FULL, rows[k], tag);
        }
    }
}

// ============================================================================
// launcher
// ============================================================================
extern "C" void kernel_launch(void* const* d_in, const int* in_sizes, int n_in,
                              void* d_out, int out_size)
{
    const int*   sent    = (const int*)d_in[0];
    const float* embed   = (const float*)d_in[1];
    const float* w_ih_f  = (const float*)d_in[2];
    const float* w_hh_f  = (const float*)d_in[3];
    const float* b_f     = (const float*)d_in[4];
    const float* w_ih_b  = (const float*)d_in[5];
    const float* w_hh_b  = (const float*)d_in[6];
    const float* b_b     = (const float*)d_in[7];
    const float* w_tag   = (const float*)d_in[8];
    const float* b_tag   = (const float*)d_in[9];
    const float* trans   = (const float*)d_in[10];
    const float* h0      = (const float*)d_in[11];
    const float* c0      = (const float*)d_in[12];
    float* out = (float*)d_out;

    dim3 g1(SEQ / 64, 1024 / 64, 2);
    px_gemm<<<g1, 256>>>(sent, embed, w_ih_f, b_f, w_ih_b, b_b);
    wtagT_kernel<<<(TTAGS * EDIM + 511) / 512, 512>>>(w_tag);
    lstm_kernel<<<16, 512>>>(w_hh_f, w_hh_b, h0, c0);
    proj_kernel<<<SEQ, 128>>>(b_tag);
    viterbi_kernel<<<1, 32>>>(trans, out, out_size);
}

// round 13
// speedup vs baseline: 1.9437x; 1.9437x over previous
#include <cuda_runtime.h>
#include <cuda_bf16.h>
#include <cstdint>

// ---------------- problem constants ----------------
#define SEQ   2048
#define EDIM  512
#define HDIM  256
#define TTAGS 32
#define TSTART 30
#define TSTOP  31
#define NEGV  (-10000.0f)

// ---------------- device scratch (no allocs allowed) ----------------
__device__ float g_px[2][SEQ][1024];     // input projections (bias fused), per dir
__device__ float g_h[2][SEQ][HDIM];      // lstm hidden outputs, per dir
__device__ float g_feats[SEQ][TTAGS];    // tag scores
__device__ float g_wtagT[EDIM][TTAGS];   // transposed tag weights
__device__ int   g_bptr[SEQ][TTAGS];     // viterbi backpointers

// ---------------- small helpers ----------------
__device__ __forceinline__ unsigned long long pack2f(float x, float y) {
    unsigned long long r;
    asm("mov.b64 %0, {%1, %2};" : "=l"(r) : "f"(x), "f"(y));
    return r;
}
__device__ __forceinline__ float2 unpack2f(unsigned long long v) {
    float2 r;
    asm("mov.b64 {%0, %1}, %2;" : "=f"(r.x), "=f"(r.y) : "l"(v));
    return r;
}
__device__ __forceinline__ void fma2(unsigned long long& d, unsigned long long a,
                                     unsigned long long b) {
    asm("fma.rn.f32x2 %0, %1, %2, %0;" : "+l"(d) : "l"(a), "l"(b));
}
__device__ __forceinline__ unsigned smem_u32(const void* p) {
    unsigned a;
    asm("{ .reg .u64 t; cvta.to.shared.u64 t, %1; cvt.u32.u64 %0, t; }"
        : "=r"(a) : "l"(p));
    return a;
}
__device__ __forceinline__ void st_cluster_f32(unsigned addr, int rank, float v) {
    unsigned ra;
    asm("mapa.shared::cluster.u32 %0, %1, %2;" : "=r"(ra) : "r"(addr), "r"(rank));
    asm volatile("st.shared::cluster.f32 [%0], %1;" :: "r"(ra), "f"(v) : "memory");
}
__device__ __forceinline__ void cluster_sync_() {
    asm volatile("barrier.cluster.arrive.aligned;" ::: "memory");
    asm volatile("barrier.cluster.wait.aligned;" ::: "memory");
}
__device__ __forceinline__ float sigmoidf_(float x) {
    return 1.0f / (1.0f + __expf(-x));
}

// ============================================================================
// Kernel 1 (REWRITTEN): px[dir][t][row] = emb[sent[t]] . w_ih[row] + b[row]
// 128x128 tile, K-tile 8, 256 threads, 8x8 microtile with packed f32x2
// accumulation (32 FFMA2 + 4 LDS.128 per kk) and float4 global loads.
// grid (16, 8, 2).
// ============================================================================
__global__ __launch_bounds__(256)
void px_gemm(const int* __restrict__ sent, const float* __restrict__ embed,
             const float* __restrict__ w_ih_f, const float* __restrict__ b_f,
             const float* __restrict__ w_ih_b, const float* __restrict__ b_b)
{
    int dir = blockIdx.z;
    const float* W  = dir ? w_ih_b : w_ih_f;
    const float* Bv = dir ? b_b    : b_f;
    int t0 = blockIdx.x * 128;
    int r0 = blockIdx.y * 128;

    __shared__ __align__(16) float As[8][128];   // k x t
    __shared__ __align__(16) float Bs[8][132];   // k x r (pad 4: 528B rows, 16B aligned)
    __shared__ int ssent[128];

    int tid = threadIdx.x;
    if (tid < 128) ssent[tid] = sent[t0 + tid];
    __syncthreads();

    int tx = tid & 15, ty = tid >> 4;    // 16 x 16 thread grid
    int lt = tid >> 1;                   // 0..127: row handled by this thread's loads
    int lh = tid & 1;                    // which k-half (float4) to load

    unsigned long long acc2[8][4];
#pragma unroll
    for (int i = 0; i < 8; i++)
#pragma unroll
        for (int j = 0; j < 4; j++) acc2[i][j] = 0ull;

    const size_t erow = (size_t)ssent[lt] * EDIM;
    const size_t wrow = (size_t)(r0 + lt) * EDIM;

    for (int k0 = 0; k0 < EDIM; k0 += 8) {
        // cooperative loads: 128 t-rows and 128 r-rows x 8 k (2 float4 each)
        float4 av = *(const float4*)&embed[erow + k0 + lh * 4];
        float4 bw = *(const float4*)&W[wrow + k0 + lh * 4];
        As[lh * 4 + 0][lt] = av.x;
        As[lh * 4 + 1][lt] = av.y;
        As[lh * 4 + 2][lt] = av.z;
        As[lh * 4 + 3][lt] = av.w;
        Bs[lh * 4 + 0][lt] = bw.x;
        Bs[lh * 4 + 1][lt] = bw.y;
        Bs[lh * 4 + 2][lt] = bw.z;
        Bs[lh * 4 + 3][lt] = bw.w;
        __syncthreads();

#pragma unroll
        for (int kk = 0; kk < 8; kk++) {
            float4 a0 = *(const float4*)&As[kk][ty * 8];
            float4 a1 = *(const float4*)&As[kk][ty * 8 + 4];
            ulonglong2 bl0 = *(const ulonglong2*)&Bs[kk][tx * 8];
            ulonglong2 bl1 = *(const ulonglong2*)&Bs[kk][tx * 8 + 4];
            unsigned long long b2[4] = { bl0.x, bl0.y, bl1.x, bl1.y };
            float a[8] = { a0.x, a0.y, a0.z, a0.w, a1.x, a1.y, a1.z, a1.w };
#pragma unroll
            for (int i = 0; i < 8; i++) {
                unsigned long long ad = pack2f(a[i], a[i]);
#pragma unroll
                for (int j = 0; j < 4; j++) fma2(acc2[i][j], ad, b2[j]);
            }
        }
        __syncthreads();
    }

    // epilogue: unpack, add bias, store two float4 per row
    float bias[8];
#pragma unroll
    for (int j = 0; j < 8; j++) bias[j] = Bv[r0 + tx * 8 + j];
#pragma unroll
    for (int i = 0; i < 8; i++) {
        int t = t0 + ty * 8 + i;
        float o[8];
#pragma unroll
        for (int j = 0; j < 4; j++) {
            float2 v = unpack2f(acc2[i][j]);
            o[2 * j]     = v.x + bias[2 * j];
            o[2 * j + 1] = v.y + bias[2 * j + 1];
        }
        float* dst = &g_px[dir][t][r0 + tx * 8];
        *(float4*)dst       = make_float4(o[0], o[1], o[2], o[3]);
        *(float4*)(dst + 4) = make_float4(o[4], o[5], o[6], o[7]);
    }
}

// ============================================================================
// Kernel 2: transpose w_tag [32,512] -> g_wtagT [512,32]
// ============================================================================
__global__ void wtagT_kernel(const float* __restrict__ w_tag)
{
    int idx = blockIdx.x * blockDim.x + threadIdx.x;
    if (idx < TTAGS * EDIM) {
        int tag = idx >> 9;
        int e   = idx & 511;
        g_wtagT[e][tag] = w_tag[idx];
    }
}

// ============================================================================
// Kernel 3: BiLSTM recurrence. EXACT 2875us best (round-9 winner): cluster.sync
// skeleton + merged warp0 reduce + px prefetch registers. FROZEN.
// ============================================================================
__global__ void __cluster_dims__(8, 1, 1) __launch_bounds__(512, 1)
lstm_kernel(const float* __restrict__ w_hh_f, const float* __restrict__ w_hh_b,
            const float* __restrict__ h0, const float* __restrict__ c0)
{
    int dir  = blockIdx.x >> 3;
    int rank = blockIdx.x & 7;
    const float* W  = dir ? w_hh_b : w_hh_f;
    const float* px = &g_px[dir][0][0];
    float* hout     = &g_h[dir][0][0];

    int tid  = threadIdx.x;
    int ks   = tid >> 7;        // 0..3  (k slice of 64)
    int r    = tid & 127;       // 0..127 (gate row within CTA)
    int grow = (r >> 5) * 256 + rank * 32 + (r & 31);   // gate row in [0,1024)

    __shared__ __align__(16) float h_sh[2][HDIM];
    __shared__ float red_sh[4][128];

    // load weight slice into registers, packed as f32x2
    unsigned long long w2[32];
    {
        const float2* wp = (const float2*)(W + (size_t)grow * HDIM + ks * 64);
#pragma unroll
        for (int i = 0; i < 32; i++) {
            float2 v = wp[i];
            w2[i] = pack2f(v.x, v.y);
        }
    }

    // initial state
    if (tid < HDIM) h_sh[0][tid] = h0[dir * HDIM + tid];
    float c = 0.0f;
    if (tid < 32) c = c0[dir * HDIM + rank * 32 + tid];

    // warp0: prefetch px for step 0 (the 4 gate rows of unit `tid`)
    float px4_0 = 0.f, px4_1 = 0.f, px4_2 = 0.f, px4_3 = 0.f;
    if (tid < 32) {
        int t0i = dir ? (SEQ - 1) : 0;
        const float* p0 = &px[(size_t)t0i * 1024 + rank * 32 + tid];
        px4_0 = __ldg(p0);
        px4_1 = __ldg(p0 + 256);
        px4_2 = __ldg(p0 + 512);
        px4_3 = __ldg(p0 + 768);
    }

    __syncthreads();
    cluster_sync_();

    int p = 0;
    for (int step = 0; step < SEQ; ++step) {
        int t = dir ? (SEQ - 1 - step) : step;

        // matvec partial: 64 MACs via 32 packed FFMA2
        unsigned long long a0 = 0ull, a1 = 0ull;
        const ulonglong2* hp = (const ulonglong2*)&h_sh[p][ks * 64];
#pragma unroll
        for (int i = 0; i < 16; i += 2) {
            ulonglong2 u = hp[i];
            ulonglong2 v = hp[i + 1];
            fma2(a0, w2[2 * i], u.x);
            fma2(a1, w2[2 * i + 1], u.y);
            fma2(a0, w2[2 * i + 2], v.x);
            fma2(a1, w2[2 * i + 3], v.y);
        }
        float2 f0 = unpack2f(a0), f1 = unpack2f(a1);
        red_sh[ks][r] = (f0.x + f0.y) + (f1.x + f1.y);
        __syncthreads();

        // warp0: reduce all 4 gates + activations + cell/hidden + broadcast
        if (tid < 32) {
            float v0 = red_sh[0][tid]      + red_sh[1][tid]      +
                       red_sh[2][tid]      + red_sh[3][tid]      + px4_0;
            float v1 = red_sh[0][32 + tid] + red_sh[1][32 + tid] +
                       red_sh[2][32 + tid] + red_sh[3][32 + tid] + px4_1;
            float v2 = red_sh[0][64 + tid] + red_sh[1][64 + tid] +
                       red_sh[2][64 + tid] + red_sh[3][64 + tid] + px4_2;
            float v3 = red_sh[0][96 + tid] + red_sh[1][96 + tid] +
                       red_sh[2][96 + tid] + red_sh[3][96 + tid] + px4_3;
            float ai = sigmoidf_(v0);
            float af = sigmoidf_(v1);
            float ag = tanhf(v2);
            float ao = sigmoidf_(v3);
            c = af * c + ai * ag;
            float hn = ao * tanhf(c);
            hout[(size_t)t * HDIM + rank * 32 + tid] = hn;
            unsigned laddr = smem_u32(&h_sh[p ^ 1][rank * 32 + tid]);
#pragma unroll
            for (int cc = 0; cc < 8; cc++) st_cluster_f32(laddr, cc, hn);

            // prefetch px for next step; LDG latency hides under cluster.sync
            if (step + 1 < SEQ) {
                int tn = dir ? (SEQ - 2 - step) : (step + 1);
                const float* p0 = &px[(size_t)tn * 1024 + rank * 32 + tid];
                px4_0 = __ldg(p0);
                px4_1 = __ldg(p0 + 256);
                px4_2 = __ldg(p0 + 512);
                px4_3 = __ldg(p0 + 768);
            }
        }
        cluster_sync_();
        p ^= 1;
    }
}

// ============================================================================
// Kernel 4: feats[t][tag] = [h_f(t) | h_b(t)] . w_tag[tag] + b_tag[tag]
// one block per timestep, 128 threads (32 tags x 4 partials)
// ============================================================================
__global__ __launch_bounds__(128)
void proj_kernel(const float* __restrict__ b_tag)
{
    int t = blockIdx.x;
    __shared__ float hs[2 * HDIM];
    __shared__ float red[4][TTAGS];
    int tid = threadIdx.x;
    for (int i = tid; i < HDIM; i += 128) {
        hs[i]        = g_h[0][t][i];
        hs[HDIM + i] = g_h[1][t][i];
    }
    __syncthreads();
    int tag = tid & 31, part = tid >> 5;
    float s = 0.0f;
    const float* hv = hs + part * 128;
    const float* wT = &g_wtagT[part * 128][tag];
#pragma unroll 8
    for (int j = 0; j < 128; j++) s += hv[j] * wT[j * TTAGS];
    red[part][tag] = s;
    __syncthreads();
    if (tid < TTAGS)
        g_feats[t][tid] = red[0][tid] + red[1][tid] + red[2][tid] + red[3][tid] +
                          b_tag[tid];
}

// ============================================================================
// Kernel 5: Viterbi forward + backtrack. Single warp (feat prefetch kept).
// ============================================================================
__global__ __launch_bounds__(32)
void viterbi_kernel(const float* __restrict__ trans, float* __restrict__ out,
                    int out_size)
{
    const unsigned FULL = 0xffffffffu;
    int lane = threadIdx.x;

    float tr[TTAGS];
#pragma unroll
    for (int j = 0; j < TTAGS; j++) tr[j] = trans[lane * TTAGS + j];

    float fv = (lane == TSTART) ? 0.0f : NEGV;
    float feat = g_feats[0][lane];

    for (int t = 0; t < SEQ; t++) {
        float feat_next = (t + 1 < SEQ) ? g_feats[t + 1][lane] : 0.0f;
        float b0 = -1e30f, b1 = -1e30f, b2 = -1e30f, b3 = -1e30f;
        int i0 = 0, i1 = 8, i2 = 16, i3 = 24;
#pragma unroll
        for (int j = 0; j < 8; j++) {
            float s0 = __shfl_sync(FULL, fv, j)      + tr[j];
            float s1 = __shfl_sync(FULL, fv, j + 8)  + tr[j + 8];
            float s2 = __shfl_sync(FULL, fv, j + 16) + tr[j + 16];
            float s3 = __shfl_sync(FULL, fv, j + 24) + tr[j + 24];
            if (s0 > b0) { b0 = s0; i0 = j; }
            if (s1 > b1) { b1 = s1; i1 = j + 8; }
            if (s2 > b2) { b2 = s2; i2 = j + 16; }
            if (s3 > b3) { b3 = s3; i3 = j + 24; }
        }
        float best = b0; int bj = i0;
        if (b1 > best) { best = b1; bj = i1; }
        if (b2 > best) { best = b2; bj = i2; }
        if (b3 > best) { best = b3; bj = i3; }
        g_bptr[t][lane] = bj;
        fv = best + feat;
        feat = feat_next;
    }

    // terminal: fv + transitions[STOP][prev]
    float term = fv + trans[TSTOP * TTAGS + lane];
    float bv = term; int bi = lane;
#pragma unroll
    for (int off = 16; off >= 1; off >>= 1) {
        float ov = __shfl_xor_sync(FULL, bv, off);
        int   oi = __shfl_xor_sync(FULL, bi, off);
        if (ov > bv || (ov == bv && oi < bi)) { bv = ov; bi = oi; }
    }
    if (lane == 0 && out_size > 0) out[0] = bv;

    // backtrack: tag_seq[S-1] = best_last; tag_seq[t-1] = bptr[t][tag_seq[t]]
    int tag = bi;
    for (int t0 = SEQ - 16; t0 >= 0; t0 -= 16) {
        int rows[16];
#pragma unroll
        for (int k = 0; k < 16; k++) rows[k] = g_bptr[t0 + k][lane];
#pragma unroll
        for (int k = 15; k >= 0; k--) {
            int t = t0 + k;
            if (lane == 0 && 1 + t < out_size) out[1 + t] = (float)tag;
            tag = __shfl_sync(FULL, rows[k], tag);
        }
    }
}

// ============================================================================
// launcher
// ============================================================================
extern "C" void kernel_launch(void* const* d_in, const int* in_sizes, int n_in,
                              void* d_out, int out_size)
{
    const int*   sent    = (const int*)d_in[0];
    const float* embed   = (const float*)d_in[1];
    const float* w_ih_f  = (const float*)d_in[2];
    const float* w_hh_f  = (const float*)d_in[3];
    const float* b_f     = (const float*)d_in[4];
    const float* w_ih_b  = (const float*)d_in[5];
    const float* w_hh_b  = (const float*)d_in[6];
    const float* b_b     = (const float*)d_in[7];
    const float* w_tag   = (const float*)d_in[8];
    const float* b_tag   = (const float*)d_in[9];
    const float* trans   = (const float*)d_in[10];
    const float* h0      = (const float*)d_in[11];
    const float* c0      = (const float*)d_in[12];
    float* out = (float*)d_out;

    dim3 g1(SEQ / 128, 1024 / 128, 2);
    px_gemm<<<g1, 256>>>(sent, embed, w_ih_f, b_f, w_ih_b, b_b);
    wtagT_kernel<<<(TTAGS * EDIM + 511) / 512, 512>>>(w_tag);
    lstm_kernel<<<16, 512>>>(w_hh_f, w_hh_b, h0, c0);
    proj_kernel<<<SEQ, 128>>>(b_tag);
    viterbi_kernel<<<1, 32>>>(trans, out, out_size);
}